// round 8
// baseline (speedup 1.0000x reference)
#include <cuda_runtime.h>
#include <math.h>
#include <float.h>

#define MAXBT 1024
__device__ float g_s  [MAXBT];
__device__ float g_px0[MAXBT];
__device__ float g_px1[MAXBT];
__device__ float g_px2[MAXBT];
__device__ float g_pt0[MAXBT];
__device__ float g_pt1[MAXBT];
__device__ float g_pt2[MAXBT];
__device__ unsigned int g_count;

typedef unsigned long long u64;

__device__ __forceinline__ u64 pk2(float lo, float hi) {
    u64 r; asm("mov.b64 %0, {%1,%2};" : "=l"(r) : "f"(lo), "f"(hi)); return r;
}
__device__ __forceinline__ void upk2(float& lo, float& hi, u64 v) {
    asm("mov.b64 {%0,%1}, %2;" : "=f"(lo), "=f"(hi) : "l"(v));
}
__device__ __forceinline__ u64 ffma2(u64 a, u64 b, u64 c) {
    u64 d; asm("fma.rn.f32x2 %0, %1, %2, %3;" : "=l"(d) : "l"(a), "l"(b), "l"(c)); return d;
}

__device__ __forceinline__ float sl1(float a, float b) {
    float d = fabsf(a - b);
    return d < 1.0f ? 0.5f * d * d : d - 0.5f;
}

__device__ __forceinline__ float warpSum(float v) {
    #pragma unroll
    for (int o = 16; o > 0; o >>= 1)
        v += __shfl_down_sync(0xffffffffu, v, o);
    return v;
}

// Embed low 9 bits of index into a float key's truncated mantissa.
__device__ __forceinline__ float embed(float d, unsigned idx) {
    return __uint_as_float((__float_as_uint(d) & 0xFFFFFE00u) | idx);
}

// Flat-balanced NN loss, ONE pred per thread (max active warps).
// grid = 148 CTAs x 1024 threads; unit u = one pred point. A CTA's units
// span <=2 tiles; both tiles' targets staged in smem banks (paired f32x2
// layout, prescaled by -2 with squared norm):
//   sA[m2] = (-2tx[2m2], -2tx[2m2+1], -2ty[2m2], -2ty[2m2+1])
//   sB[m2] = (-2tz[2m2], -2tz[2m2+1],  tn[2m2],  tn[2m2+1])
// Argmin: key = tn - 2 x.t (signed, monotone in dist^2), low 9 mantissa bits
// = m2 counter; 2 independent FMNMX chains (even/odd parity).
__global__ __launch_bounds__(1024, 1)
void nn_loss_kernel(const float* __restrict__ X,
                    const float* __restrict__ T,
                    const float* __restrict__ W,
                    float* __restrict__ out,
                    int N, int BT, int B,
                    int totalUnits, int unitsPerCta)
{
    extern __shared__ float4 smem4[];
    __shared__ int isLast;

    const int tid  = threadIdx.x;
    const int bid  = blockIdx.x;
    const int half = N >> 1;   // 512

    int uStart = bid * unitsPerCta;
    int myU = totalUnits - uStart;
    if (myU > unitsPerCta) myU = unitsPerCta;
    if (myU < 0) myU = 0;

    const int tileLo = uStart >> 10;
    const int tileHi = (myU > 0) ? ((uStart + myU - 1) >> 10) : tileLo;

    // ---- Stage tileLo into bank0 (each thread stages target tid) ----
    {
        const float* Tb = T + (size_t)tileLo * N * 3;
        float4* sA = smem4;
        float4* sB = smem4 + half;
        int i = tid;
        float t0 = Tb[i * 3 + 0], t1 = Tb[i * 3 + 1], t2 = Tb[i * 3 + 2];
        float tn = fmaf(t0, t0, fmaf(t1, t1, t2 * t2));
        int m2 = i >> 1, p = i & 1;
        float* A  = (float*)&sA[m2];
        float* Bp = (float*)&sB[m2];
        A[p] = -2.0f * t0;  A[2 + p] = -2.0f * t1;
        Bp[p] = -2.0f * t2; Bp[2 + p] = tn;
    }
    // ---- Stage tileHi into bank1 if the CTA spans two tiles ----
    if (tileHi != tileLo) {
        const float* Tb = T + (size_t)tileHi * N * 3;
        float4* sA = smem4 + 2 * half;
        float4* sB = smem4 + 3 * half;
        int i = tid;
        float t0 = Tb[i * 3 + 0], t1 = Tb[i * 3 + 1], t2 = Tb[i * 3 + 2];
        float tn = fmaf(t0, t0, fmaf(t1, t1, t2 * t2));
        int m2 = i >> 1, p = i & 1;
        float* A  = (float*)&sA[m2];
        float* Bp = (float*)&sB[m2];
        A[p] = -2.0f * t0;  A[2 + p] = -2.0f * t1;
        Bp[p] = -2.0f * t2; Bp[2 + p] = tn;
    }
    __syncthreads();

    float s = 0.0f;
    float sx0 = 0.0f, sx1 = 0.0f, sx2 = 0.0f;
    float st0 = 0.0f, st1 = 0.0f, st2 = 0.0f;
    int tile = -1;

    if (tid < myU) {
        const int u = uStart + tid;
        tile = u >> 10;

        float xa0 = X[(size_t)u * 3 + 0];
        float xa1 = X[(size_t)u * 3 + 1];
        float xa2 = X[(size_t)u * 3 + 2];
        st0 = T[(size_t)u * 3 + 0];
        st1 = T[(size_t)u * 3 + 1];
        st2 = T[(size_t)u * 3 + 2];
        sx0 = xa0; sx1 = xa1; sx2 = xa2;

        const float4* bank = (tile == tileLo) ? smem4 : (smem4 + 2 * half);
        const ulonglong2* pA = (const ulonglong2*)bank;
        const ulonglong2* pB = (const ulonglong2*)(bank + half);

        u64 A0 = pk2(xa0, xa0), A1 = pk2(xa1, xa1), A2 = pk2(xa2, xa2);

        float b0 = FLT_MAX, b1 = FLT_MAX;   // even/odd chains

        #pragma unroll 8
        for (int m2 = 0; m2 < half; ++m2) {
            ulonglong2 a = pA[m2];   // (tx_e,tx_o),(ty_e,ty_o) prescaled by -2
            ulonglong2 b = pB[m2];   // (tz_e,tz_o),(tn_e,tn_o)
            u64 dp = ffma2(A0, a.x, ffma2(A1, a.y, ffma2(A2, b.x, b.y)));
            float d0, d1;
            upk2(d0, d1, dp);
            unsigned mu = (unsigned)m2;
            b0 = fminf(b0, embed(d0, mu));
            b1 = fminf(b1, embed(d1, mu));
        }

        int idxA;
        {
            float k = b0; int h = 0;
            if (b1 < b0) { k = b1; h = 1; }
            idxA = (int)((__float_as_uint(k) & 511u) << 1) | h;
        }

        {
            int m2 = idxA >> 1, p = idxA & 1;
            const float* Af = (const float*)&bank[m2];
            const float* Bf = (const float*)&bank[half + m2];
            s = sl1(xa0, -0.5f * Af[p]) + sl1(xa1, -0.5f * Af[2 + p]) + sl1(xa2, -0.5f * Bf[p]);
        }
    }

    // ---- Per-tile accumulation: warp-uniform fast path, per-lane fallback ----
    {
        int t0 = __shfl_sync(0xffffffffu, tile, 0);
        bool uni = __all_sync(0xffffffffu, tile == t0);
        if (uni) {
            float rs  = warpSum(s);
            float r0  = warpSum(sx0), r1 = warpSum(sx1), r2 = warpSum(sx2);
            float r3  = warpSum(st0), r4 = warpSum(st1), r5 = warpSum(st2);
            if ((tid & 31) == 0 && t0 >= 0) {
                atomicAdd(&g_s[t0],   rs);
                atomicAdd(&g_px0[t0], r0); atomicAdd(&g_px1[t0], r1); atomicAdd(&g_px2[t0], r2);
                atomicAdd(&g_pt0[t0], r3); atomicAdd(&g_pt1[t0], r4); atomicAdd(&g_pt2[t0], r5);
            }
        } else if (tile >= 0) {
            atomicAdd(&g_s[tile],   s);
            atomicAdd(&g_px0[tile], sx0); atomicAdd(&g_px1[tile], sx1); atomicAdd(&g_px2[tile], sx2);
            atomicAdd(&g_pt0[tile], st0); atomicAdd(&g_pt1[tile], st1); atomicAdd(&g_pt2[tile], st2);
        }
    }

    __syncthreads();
    if (tid == 0) {
        __threadfence();
        unsigned int prev = atomicAdd(&g_count, 1u);
        isLast = (prev == (unsigned int)(gridDim.x - 1)) ? 1 : 0;
    }
    __syncthreads();

    if (isLast && tid < 32) {
        __threadfence();
        float v1 = 0.0f, v2 = 0.0f;
        float invN = 1.0f / (float)N;
        for (int i = tid; i < BT; i += 32) {
            float ss = g_s[i];
            float a0 = g_px0[i], a1 = g_px1[i], a2 = g_px2[i];
            float c0 = g_pt0[i], c1 = g_pt1[i], c2 = g_pt2[i];
            g_s[i] = 0.0f;
            g_px0[i] = 0.0f; g_px1[i] = 0.0f; g_px2[i] = 0.0f;
            g_pt0[i] = 0.0f; g_pt1[i] = 0.0f; g_pt2[i] = 0.0f;
            v1 += W[i] * ss;
            v2 += sl1(a0 * invN, c0 * invN)
                + sl1(a1 * invN, c1 * invN)
                + sl1(a2 * invN, c2 * invN);
        }
        #pragma unroll
        for (int o = 16; o > 0; o >>= 1) {
            v1 += __shfl_down_sync(0xffffffffu, v1, o);
            v2 += __shfl_down_sync(0xffffffffu, v2, o);
        }
        if (tid == 0) {
            out[0] = v1 / (3.0f * (float)N * (float)B);
            out[1] = v2 / ((float)B * 3.0f);
            g_count = 0;
        }
    }
}

extern "C" void kernel_launch(void* const* d_in, const int* in_sizes, int n_in,
                              void* d_out, int out_size)
{
    const float* X = (const float*)d_in[0];   // [B,T,N,3]
    const float* T = (const float*)d_in[1];   // [B,T,N,3]
    const float* W = (const float*)d_in[2];   // [B,T]
    float* out = (float*)d_out;

    const int BT = in_sizes[2];               // 112
    const int N  = in_sizes[0] / (BT * 3);    // 1024
    const int B  = 4;

    const int NSM = 148;
    const int totalUnits = BT * N;                        // 114688 preds
    const int unitsPerCta = (totalUnits + NSM - 1) / NSM; // 775

    size_t smem = 2 * (size_t)N * sizeof(float4);         // 32 KB (2 banks)
    nn_loss_kernel<<<NSM, 1024, smem>>>(X, T, W, out, N, BT, B,
                                        totalUnits, unitsPerCta);
}

// round 10
// speedup vs baseline: 1.1775x; 1.1775x over previous
#include <cuda_runtime.h>
#include <math.h>
#include <float.h>

#define MAXBT 1024
__device__ float g_s  [MAXBT];
__device__ float g_px0[MAXBT];
__device__ float g_px1[MAXBT];
__device__ float g_px2[MAXBT];
__device__ float g_pt0[MAXBT];
__device__ float g_pt1[MAXBT];
__device__ float g_pt2[MAXBT];
__device__ unsigned int g_count;

typedef unsigned long long u64;

__device__ __forceinline__ u64 pk2(float lo, float hi) {
    u64 r; asm("mov.b64 %0, {%1,%2};" : "=l"(r) : "f"(lo), "f"(hi)); return r;
}
__device__ __forceinline__ void upk2(float& lo, float& hi, u64 v) {
    asm("mov.b64 {%0,%1}, %2;" : "=f"(lo), "=f"(hi) : "l"(v));
}
__device__ __forceinline__ u64 ffma2(u64 a, u64 b, u64 c) {
    u64 d; asm("fma.rn.f32x2 %0, %1, %2, %3;" : "=l"(d) : "l"(a), "l"(b), "l"(c)); return d;
}

__device__ __forceinline__ float sl1(float a, float b) {
    float d = fabsf(a - b);
    return d < 1.0f ? 0.5f * d * d : d - 0.5f;
}

__device__ __forceinline__ float warpSum(float v) {
    #pragma unroll
    for (int o = 16; o > 0; o >>= 1)
        v += __shfl_down_sync(0xffffffffu, v, o);
    return v;
}

// Embed low 7 bits (block id) into a float key's truncated mantissa.
__device__ __forceinline__ float embed7(float d, unsigned blk) {
    return __uint_as_float((__float_as_uint(d) & 0xFFFFFF80u) | blk);
}

// Min of a packed pair + fold into an 8-way tree (unpack is register aliasing,
// free at SASS level; fminf = FMNMX on the alu pipe).
__device__ __forceinline__ float min8(u64 d0, u64 d1, u64 d2, u64 d3) {
    float a0, a1, b0, b1, c0, c1, e0, e1;
    upk2(a0, a1, d0); upk2(b0, b1, d1); upk2(c0, c1, d2); upk2(e0, e1, d3);
    float m0 = fminf(a0, a1);
    float m1 = fminf(b0, b1);
    float m2 = fminf(c0, c1);
    float m3 = fminf(e0, e1);
    return fminf(fminf(m0, m1), fminf(m2, m3));
}

// Exact scalar rescan of one tournament block (4 m2 pairs = 8 targets).
// Same FFMA chain as the packed loop -> bit-identical distances; strict '<'
// ascending index reproduces first-min tie-break within the block.
__device__ __forceinline__ int rescan_block(const float4* bank, int half, int blk,
                                            float x0, float x1, float x2) {
    float best = FLT_MAX; int idx = 0;
    #pragma unroll
    for (int j = 0; j < 4; ++j) {
        int m2 = (blk << 2) + j;
        const float* Af = (const float*)&bank[m2];
        const float* Bf = (const float*)&bank[half + m2];
        #pragma unroll
        for (int p = 0; p < 2; ++p) {
            float d = fmaf(x0, Af[p], fmaf(x1, Af[2 + p], fmaf(x2, Bf[p], Bf[2 + p])));
            int i = (m2 << 1) | p;
            if (d < best) { best = d; idx = i; }
        }
    }
    return idx;
}

// Flat-balanced NN loss, 2 preds/thread, tournament argmin.
// Work unit = adjacent pred pair (2u,2u+1). grid = 148 CTAs x 512 threads.
// Targets staged in <=2 smem banks (paired f32x2 layout, prescaled by -2,
// with squared norm):
//   sA[m2] = (-2tx[2m2], -2tx[2m2+1], -2ty[2m2], -2ty[2m2+1])
//   sB[m2] = (-2tz[2m2], -2tz[2m2+1],  tn[2m2],  tn[2m2+1])
// Scan: blocks of 4 m2 (8 targets). Keys tn-2x.t reduced with an FMNMX tree
// (no index tracking), then ONE truncated-key|block-id update per block.
// Winning block rescanned exactly at the end.
__global__ __launch_bounds__(512, 1)
void nn_loss_kernel(const float* __restrict__ X,
                    const float* __restrict__ T,
                    const float* __restrict__ W,
                    float* __restrict__ out,
                    int N, int BT, int B,
                    int totalUnits, int unitsPerCta)
{
    extern __shared__ float4 smem4[];
    __shared__ int isLast;

    const int tid  = threadIdx.x;
    const int bid  = blockIdx.x;
    const int half = N >> 1;   // 512

    int uStart = bid * unitsPerCta;
    int myU = totalUnits - uStart;
    if (myU > unitsPerCta) myU = unitsPerCta;
    if (myU < 0) myU = 0;

    const int tileLo = (uStart * 2) >> 10;
    const int tileHi = (myU > 0) ? (((uStart + myU) * 2 - 1) >> 10) : tileLo;

    // ---- Stage tileLo into bank0 ----
    {
        const float* Tb = T + (size_t)tileLo * N * 3;
        float4* sA = smem4;
        float4* sB = smem4 + half;
        #pragma unroll
        for (int r = 0; r < 2; ++r) {
            int i = tid + r * half;
            float t0 = Tb[i * 3 + 0], t1 = Tb[i * 3 + 1], t2 = Tb[i * 3 + 2];
            float tn = fmaf(t0, t0, fmaf(t1, t1, t2 * t2));
            int m2 = i >> 1, p = i & 1;
            float* A  = (float*)&sA[m2];
            float* Bp = (float*)&sB[m2];
            A[p] = -2.0f * t0;  A[2 + p] = -2.0f * t1;
            Bp[p] = -2.0f * t2; Bp[2 + p] = tn;
        }
    }
    // ---- Stage tileHi into bank1 if the CTA spans two tiles ----
    if (tileHi != tileLo) {
        const float* Tb = T + (size_t)tileHi * N * 3;
        float4* sA = smem4 + 2 * half;
        float4* sB = smem4 + 3 * half;
        #pragma unroll
        for (int r = 0; r < 2; ++r) {
            int i = tid + r * half;
            float t0 = Tb[i * 3 + 0], t1 = Tb[i * 3 + 1], t2 = Tb[i * 3 + 2];
            float tn = fmaf(t0, t0, fmaf(t1, t1, t2 * t2));
            int m2 = i >> 1, p = i & 1;
            float* A  = (float*)&sA[m2];
            float* Bp = (float*)&sB[m2];
            A[p] = -2.0f * t0;  A[2 + p] = -2.0f * t1;
            Bp[p] = -2.0f * t2; Bp[2 + p] = tn;
        }
    }
    __syncthreads();

    float s = 0.0f;
    float sx0 = 0.0f, sx1 = 0.0f, sx2 = 0.0f;
    float st0 = 0.0f, st1 = 0.0f, st2 = 0.0f;
    int tile = -1;

    if (tid < myU) {
        const int u = uStart + tid;
        tile = (u * 2) >> 10;

        const float2* Xp = (const float2*)(X + (size_t)u * 6);
        float2 p0 = Xp[0], p1 = Xp[1], p2 = Xp[2];
        float xa0 = p0.x, xa1 = p0.y, xa2 = p1.x;
        float xb0 = p1.y, xb1 = p2.x, xb2 = p2.y;

        const float2* Tp = (const float2*)(T + (size_t)u * 6);
        float2 q0 = Tp[0], q1 = Tp[1], q2 = Tp[2];
        st0 = q0.x + q1.y; st1 = q0.y + q2.x; st2 = q1.x + q2.y;
        sx0 = xa0 + xb0;   sx1 = xa1 + xb1;   sx2 = xa2 + xb2;

        const float4* bank = (tile == tileLo) ? smem4 : (smem4 + 2 * half);
        const ulonglong2* pA = (const ulonglong2*)bank;
        const ulonglong2* pB = (const ulonglong2*)(bank + half);

        u64 A0 = pk2(xa0, xa0), A1 = pk2(xa1, xa1), A2 = pk2(xa2, xa2);
        u64 B0 = pk2(xb0, xb0), B1 = pk2(xb1, xb1), B2 = pk2(xb2, xb2);

        float bestA = FLT_MAX, bestB = FLT_MAX;  // truncated-key | block-id

        const int nblk = half >> 2;   // 128 blocks of 4 m2 (8 targets each)
        #pragma unroll 2
        for (int blk = 0; blk < nblk; ++blk) {
            int m2 = blk << 2;
            ulonglong2 a0 = pA[m2],     b0v = pB[m2];
            ulonglong2 a1 = pA[m2 + 1], b1v = pB[m2 + 1];
            ulonglong2 a2 = pA[m2 + 2], b2v = pB[m2 + 2];
            ulonglong2 a3 = pA[m2 + 3], b3v = pB[m2 + 3];

            u64 dA0 = ffma2(A0, a0.x, ffma2(A1, a0.y, ffma2(A2, b0v.x, b0v.y)));
            u64 dA1 = ffma2(A0, a1.x, ffma2(A1, a1.y, ffma2(A2, b1v.x, b1v.y)));
            u64 dA2 = ffma2(A0, a2.x, ffma2(A1, a2.y, ffma2(A2, b2v.x, b2v.y)));
            u64 dA3 = ffma2(A0, a3.x, ffma2(A1, a3.y, ffma2(A2, b3v.x, b3v.y)));
            u64 dB0 = ffma2(B0, a0.x, ffma2(B1, a0.y, ffma2(B2, b0v.x, b0v.y)));
            u64 dB1 = ffma2(B0, a1.x, ffma2(B1, a1.y, ffma2(B2, b1v.x, b1v.y)));
            u64 dB2 = ffma2(B0, a2.x, ffma2(B1, a2.y, ffma2(B2, b2v.x, b2v.y)));
            u64 dB3 = ffma2(B0, a3.x, ffma2(B1, a3.y, ffma2(B2, b3v.x, b3v.y)));

            float mA = min8(dA0, dA1, dA2, dA3);
            float mB = min8(dB0, dB1, dB2, dB3);

            bestA = fminf(bestA, embed7(mA, (unsigned)blk));
            bestB = fminf(bestB, embed7(mB, (unsigned)blk));
        }

        int blkA = (int)(__float_as_uint(bestA) & 127u);
        int blkB = (int)(__float_as_uint(bestB) & 127u);
        int idxA = rescan_block(bank, half, blkA, xa0, xa1, xa2);
        int idxB = rescan_block(bank, half, blkB, xb0, xb1, xb2);

        {
            int m2 = idxA >> 1, p = idxA & 1;
            const float* Af = (const float*)&bank[m2];
            const float* Bf = (const float*)&bank[half + m2];
            s = sl1(xa0, -0.5f * Af[p]) + sl1(xa1, -0.5f * Af[2 + p]) + sl1(xa2, -0.5f * Bf[p]);
            m2 = idxB >> 1; p = idxB & 1;
            Af = (const float*)&bank[m2];
            Bf = (const float*)&bank[half + m2];
            s += sl1(xb0, -0.5f * Af[p]) + sl1(xb1, -0.5f * Af[2 + p]) + sl1(xb2, -0.5f * Bf[p]);
        }
    }

    // ---- Per-tile accumulation: warp-uniform fast path, per-lane fallback ----
    {
        int t0 = __shfl_sync(0xffffffffu, tile, 0);
        bool uni = __all_sync(0xffffffffu, tile == t0);
        if (uni) {
            float rs  = warpSum(s);
            float r0  = warpSum(sx0), r1 = warpSum(sx1), r2 = warpSum(sx2);
            float r3  = warpSum(st0), r4 = warpSum(st1), r5 = warpSum(st2);
            if ((tid & 31) == 0 && t0 >= 0) {
                atomicAdd(&g_s[t0],   rs);
                atomicAdd(&g_px0[t0], r0); atomicAdd(&g_px1[t0], r1); atomicAdd(&g_px2[t0], r2);
                atomicAdd(&g_pt0[t0], r3); atomicAdd(&g_pt1[t0], r4); atomicAdd(&g_pt2[t0], r5);
            }
        } else if (tile >= 0) {
            atomicAdd(&g_s[tile],   s);
            atomicAdd(&g_px0[tile], sx0); atomicAdd(&g_px1[tile], sx1); atomicAdd(&g_px2[tile], sx2);
            atomicAdd(&g_pt0[tile], st0); atomicAdd(&g_pt1[tile], st1); atomicAdd(&g_pt2[tile], st2);
        }
    }

    __syncthreads();
    if (tid == 0) {
        __threadfence();
        unsigned int prev = atomicAdd(&g_count, 1u);
        isLast = (prev == (unsigned int)(gridDim.x - 1)) ? 1 : 0;
    }
    __syncthreads();

    if (isLast && tid < 32) {
        __threadfence();
        float v1 = 0.0f, v2 = 0.0f;
        float invN = 1.0f / (float)N;
        for (int i = tid; i < BT; i += 32) {
            float ss = g_s[i];
            float a0 = g_px0[i], a1 = g_px1[i], a2 = g_px2[i];
            float c0 = g_pt0[i], c1 = g_pt1[i], c2 = g_pt2[i];
            g_s[i] = 0.0f;
            g_px0[i] = 0.0f; g_px1[i] = 0.0f; g_px2[i] = 0.0f;
            g_pt0[i] = 0.0f; g_pt1[i] = 0.0f; g_pt2[i] = 0.0f;
            v1 += W[i] * ss;
            v2 += sl1(a0 * invN, c0 * invN)
                + sl1(a1 * invN, c1 * invN)
                + sl1(a2 * invN, c2 * invN);
        }
        #pragma unroll
        for (int o = 16; o > 0; o >>= 1) {
            v1 += __shfl_down_sync(0xffffffffu, v1, o);
            v2 += __shfl_down_sync(0xffffffffu, v2, o);
        }
        if (tid == 0) {
            out[0] = v1 / (3.0f * (float)N * (float)B);
            out[1] = v2 / ((float)B * 3.0f);
            g_count = 0;
        }
    }
}

extern "C" void kernel_launch(void* const* d_in, const int* in_sizes, int n_in,
                              void* d_out, int out_size)
{
    const float* X = (const float*)d_in[0];   // [B,T,N,3]
    const float* T = (const float*)d_in[1];   // [B,T,N,3]
    const float* W = (const float*)d_in[2];   // [B,T]
    float* out = (float*)d_out;

    const int BT = in_sizes[2];               // 112
    const int N  = in_sizes[0] / (BT * 3);    // 1024
    const int B  = 4;

    const int NSM = 148;
    const int totalUnits = BT * (N / 2);                 // 57344
    const int unitsPerCta = (totalUnits + NSM - 1) / NSM; // 388

    size_t smem = 2 * (size_t)N * sizeof(float4);        // 32 KB (2 banks)
    nn_loss_kernel<<<NSM, 512, smem>>>(X, T, W, out, N, BT, B,
                                       totalUnits, unitsPerCta);
}

// round 11
// speedup vs baseline: 1.2158x; 1.0325x over previous
#include <cuda_runtime.h>
#include <math.h>
#include <float.h>

#define MAXBT 1024
__device__ float g_s  [MAXBT];
__device__ float g_px0[MAXBT];
__device__ float g_px1[MAXBT];
__device__ float g_px2[MAXBT];
__device__ float g_pt0[MAXBT];
__device__ float g_pt1[MAXBT];
__device__ float g_pt2[MAXBT];
__device__ unsigned int g_count;

typedef unsigned long long u64;

__device__ __forceinline__ u64 pk2(float lo, float hi) {
    u64 r; asm("mov.b64 %0, {%1,%2};" : "=l"(r) : "f"(lo), "f"(hi)); return r;
}
__device__ __forceinline__ void upk2(float& lo, float& hi, u64 v) {
    asm("mov.b64 {%0,%1}, %2;" : "=f"(lo), "=f"(hi) : "l"(v));
}
__device__ __forceinline__ u64 ffma2(u64 a, u64 b, u64 c) {
    u64 d; asm("fma.rn.f32x2 %0, %1, %2, %3;" : "=l"(d) : "l"(a), "l"(b), "l"(c)); return d;
}

__device__ __forceinline__ float sl1(float a, float b) {
    float d = fabsf(a - b);
    return d < 1.0f ? 0.5f * d * d : d - 0.5f;
}

__device__ __forceinline__ float warpSum(float v) {
    #pragma unroll
    for (int o = 16; o > 0; o >>= 1)
        v += __shfl_down_sync(0xffffffffu, v, o);
    return v;
}

// Embed low 7 bits (block id) into a float key's truncated mantissa.
__device__ __forceinline__ float embed7(float d, unsigned blk) {
    return __uint_as_float((__float_as_uint(d) & 0xFFFFFF80u) | blk);
}

// Min-fold of 4 packed distance pairs (unpack = register aliasing, free).
__device__ __forceinline__ float min8(u64 d0, u64 d1, u64 d2, u64 d3) {
    float a0, a1, b0, b1, c0, c1, e0, e1;
    upk2(a0, a1, d0); upk2(b0, b1, d1); upk2(c0, c1, d2); upk2(e0, e1, d3);
    return fminf(fminf(fminf(a0, a1), fminf(b0, b1)),
                 fminf(fminf(c0, c1), fminf(e0, e1)));
}

// One tournament block: 24 FFMA2 + 2 min trees, updates bestA/bestB.
struct Blk {
    ulonglong2 a0, a1, a2, a3;   // (tx_e,tx_o),(ty_e,ty_o) per m2 (prescaled -2)
    ulonglong2 b0, b1, b2, b3;   // (tz_e,tz_o),(tn_e,tn_o) per m2
};

__device__ __forceinline__ Blk load_blk(const ulonglong2* pA, const ulonglong2* pB, int blk) {
    Blk r;
    int m2 = blk << 2;
    r.a0 = pA[m2];     r.b0 = pB[m2];
    r.a1 = pA[m2 + 1]; r.b1 = pB[m2 + 1];
    r.a2 = pA[m2 + 2]; r.b2 = pB[m2 + 2];
    r.a3 = pA[m2 + 3]; r.b3 = pB[m2 + 3];
    return r;
}

__device__ __forceinline__ void compute_blk(
    const Blk& c, u64 A0, u64 A1, u64 A2, u64 B0, u64 B1, u64 B2,
    unsigned blk, float& bestA, float& bestB)
{
    u64 dA0 = ffma2(A0, c.a0.x, ffma2(A1, c.a0.y, ffma2(A2, c.b0.x, c.b0.y)));
    u64 dA1 = ffma2(A0, c.a1.x, ffma2(A1, c.a1.y, ffma2(A2, c.b1.x, c.b1.y)));
    u64 dA2 = ffma2(A0, c.a2.x, ffma2(A1, c.a2.y, ffma2(A2, c.b2.x, c.b2.y)));
    u64 dA3 = ffma2(A0, c.a3.x, ffma2(A1, c.a3.y, ffma2(A2, c.b3.x, c.b3.y)));
    u64 dB0 = ffma2(B0, c.a0.x, ffma2(B1, c.a0.y, ffma2(B2, c.b0.x, c.b0.y)));
    u64 dB1 = ffma2(B0, c.a1.x, ffma2(B1, c.a1.y, ffma2(B2, c.b1.x, c.b1.y)));
    u64 dB2 = ffma2(B0, c.a2.x, ffma2(B1, c.a2.y, ffma2(B2, c.b2.x, c.b2.y)));
    u64 dB3 = ffma2(B0, c.a3.x, ffma2(B1, c.a3.y, ffma2(B2, c.b3.x, c.b3.y)));
    bestA = fminf(bestA, embed7(min8(dA0, dA1, dA2, dA3), blk));
    bestB = fminf(bestB, embed7(min8(dB0, dB1, dB2, dB3), blk));
}

// Exact scalar rescan of one tournament block (8 targets).
__device__ __forceinline__ int rescan_block(const float4* bank, int half, int blk,
                                            float x0, float x1, float x2) {
    float best = FLT_MAX; int idx = 0;
    #pragma unroll
    for (int j = 0; j < 4; ++j) {
        int m2 = (blk << 2) + j;
        const float* Af = (const float*)&bank[m2];
        const float* Bf = (const float*)&bank[half + m2];
        #pragma unroll
        for (int p = 0; p < 2; ++p) {
            float d = fmaf(x0, Af[p], fmaf(x1, Af[2 + p], fmaf(x2, Bf[p], Bf[2 + p])));
            int i = (m2 << 1) | p;
            if (d < best) { best = d; idx = i; }
        }
    }
    return idx;
}

// Flat-balanced NN loss, 2 preds/thread, tournament argmin with explicit
// double-buffered smem prefetch (block i+1 loads overlap block i compute).
__global__ __launch_bounds__(512, 1)
void nn_loss_kernel(const float* __restrict__ X,
                    const float* __restrict__ T,
                    const float* __restrict__ W,
                    float* __restrict__ out,
                    int N, int BT, int B,
                    int totalUnits, int unitsPerCta)
{
    extern __shared__ float4 smem4[];
    __shared__ int isLast;

    const int tid  = threadIdx.x;
    const int bid  = blockIdx.x;
    const int half = N >> 1;   // 512

    int uStart = bid * unitsPerCta;
    int myU = totalUnits - uStart;
    if (myU > unitsPerCta) myU = unitsPerCta;
    if (myU < 0) myU = 0;

    const int tileLo = (uStart * 2) >> 10;
    const int tileHi = (myU > 0) ? (((uStart + myU) * 2 - 1) >> 10) : tileLo;

    // ---- Stage tileLo into bank0 ----
    {
        const float* Tb = T + (size_t)tileLo * N * 3;
        float4* sA = smem4;
        float4* sB = smem4 + half;
        #pragma unroll
        for (int r = 0; r < 2; ++r) {
            int i = tid + r * half;
            float t0 = Tb[i * 3 + 0], t1 = Tb[i * 3 + 1], t2 = Tb[i * 3 + 2];
            float tn = fmaf(t0, t0, fmaf(t1, t1, t2 * t2));
            int m2 = i >> 1, p = i & 1;
            float* A  = (float*)&sA[m2];
            float* Bp = (float*)&sB[m2];
            A[p] = -2.0f * t0;  A[2 + p] = -2.0f * t1;
            Bp[p] = -2.0f * t2; Bp[2 + p] = tn;
        }
    }
    // ---- Stage tileHi into bank1 if the CTA spans two tiles ----
    if (tileHi != tileLo) {
        const float* Tb = T + (size_t)tileHi * N * 3;
        float4* sA = smem4 + 2 * half;
        float4* sB = smem4 + 3 * half;
        #pragma unroll
        for (int r = 0; r < 2; ++r) {
            int i = tid + r * half;
            float t0 = Tb[i * 3 + 0], t1 = Tb[i * 3 + 1], t2 = Tb[i * 3 + 2];
            float tn = fmaf(t0, t0, fmaf(t1, t1, t2 * t2));
            int m2 = i >> 1, p = i & 1;
            float* A  = (float*)&sA[m2];
            float* Bp = (float*)&sB[m2];
            A[p] = -2.0f * t0;  A[2 + p] = -2.0f * t1;
            Bp[p] = -2.0f * t2; Bp[2 + p] = tn;
        }
    }
    __syncthreads();

    float s = 0.0f;
    float sx0 = 0.0f, sx1 = 0.0f, sx2 = 0.0f;
    float st0 = 0.0f, st1 = 0.0f, st2 = 0.0f;
    int tile = -1;

    if (tid < myU) {
        const int u = uStart + tid;
        tile = (u * 2) >> 10;

        const float2* Xp = (const float2*)(X + (size_t)u * 6);
        float2 p0 = Xp[0], p1 = Xp[1], p2 = Xp[2];
        float xa0 = p0.x, xa1 = p0.y, xa2 = p1.x;
        float xb0 = p1.y, xb1 = p2.x, xb2 = p2.y;

        const float2* Tp = (const float2*)(T + (size_t)u * 6);
        float2 q0 = Tp[0], q1 = Tp[1], q2 = Tp[2];
        st0 = q0.x + q1.y; st1 = q0.y + q2.x; st2 = q1.x + q2.y;
        sx0 = xa0 + xb0;   sx1 = xa1 + xb1;   sx2 = xa2 + xb2;

        const float4* bank = (tile == tileLo) ? smem4 : (smem4 + 2 * half);
        const ulonglong2* pA = (const ulonglong2*)bank;
        const ulonglong2* pB = (const ulonglong2*)(bank + half);

        u64 A0 = pk2(xa0, xa0), A1 = pk2(xa1, xa1), A2 = pk2(xa2, xa2);
        u64 B0 = pk2(xb0, xb0), B1 = pk2(xb1, xb1), B2 = pk2(xb2, xb2);

        float bestA = FLT_MAX, bestB = FLT_MAX;

        const int nblk = half >> 2;   // 128 blocks of 8 targets
        Blk cur = load_blk(pA, pB, 0);
        #pragma unroll 2
        for (int blk = 0; blk < nblk - 1; ++blk) {
            Blk nxt = load_blk(pA, pB, blk + 1);    // prefetch next block
            compute_blk(cur, A0, A1, A2, B0, B1, B2, (unsigned)blk, bestA, bestB);
            cur = nxt;
        }
        compute_blk(cur, A0, A1, A2, B0, B1, B2, (unsigned)(nblk - 1), bestA, bestB);

        int blkA = (int)(__float_as_uint(bestA) & 127u);
        int blkB = (int)(__float_as_uint(bestB) & 127u);
        int idxA = rescan_block(bank, half, blkA, xa0, xa1, xa2);
        int idxB = rescan_block(bank, half, blkB, xb0, xb1, xb2);

        {
            int m2 = idxA >> 1, p = idxA & 1;
            const float* Af = (const float*)&bank[m2];
            const float* Bf = (const float*)&bank[half + m2];
            s = sl1(xa0, -0.5f * Af[p]) + sl1(xa1, -0.5f * Af[2 + p]) + sl1(xa2, -0.5f * Bf[p]);
            m2 = idxB >> 1; p = idxB & 1;
            Af = (const float*)&bank[m2];
            Bf = (const float*)&bank[half + m2];
            s += sl1(xb0, -0.5f * Af[p]) + sl1(xb1, -0.5f * Af[2 + p]) + sl1(xb2, -0.5f * Bf[p]);
        }
    }

    // ---- Per-tile accumulation: warp-uniform fast path, per-lane fallback ----
    {
        int t0 = __shfl_sync(0xffffffffu, tile, 0);
        bool uni = __all_sync(0xffffffffu, tile == t0);
        if (uni) {
            float rs  = warpSum(s);
            float r0  = warpSum(sx0), r1 = warpSum(sx1), r2 = warpSum(sx2);
            float r3  = warpSum(st0), r4 = warpSum(st1), r5 = warpSum(st2);
            if ((tid & 31) == 0 && t0 >= 0) {
                atomicAdd(&g_s[t0],   rs);
                atomicAdd(&g_px0[t0], r0); atomicAdd(&g_px1[t0], r1); atomicAdd(&g_px2[t0], r2);
                atomicAdd(&g_pt0[t0], r3); atomicAdd(&g_pt1[t0], r4); atomicAdd(&g_pt2[t0], r5);
            }
        } else if (tile >= 0) {
            atomicAdd(&g_s[tile],   s);
            atomicAdd(&g_px0[tile], sx0); atomicAdd(&g_px1[tile], sx1); atomicAdd(&g_px2[tile], sx2);
            atomicAdd(&g_pt0[tile], st0); atomicAdd(&g_pt1[tile], st1); atomicAdd(&g_pt2[tile], st2);
        }
    }

    __syncthreads();
    if (tid == 0) {
        __threadfence();
        unsigned int prev = atomicAdd(&g_count, 1u);
        isLast = (prev == (unsigned int)(gridDim.x - 1)) ? 1 : 0;
    }
    __syncthreads();

    if (isLast && tid < 32) {
        __threadfence();
        float v1 = 0.0f, v2 = 0.0f;
        float invN = 1.0f / (float)N;
        for (int i = tid; i < BT; i += 32) {
            float ss = g_s[i];
            float a0 = g_px0[i], a1 = g_px1[i], a2 = g_px2[i];
            float c0 = g_pt0[i], c1 = g_pt1[i], c2 = g_pt2[i];
            g_s[i] = 0.0f;
            g_px0[i] = 0.0f; g_px1[i] = 0.0f; g_px2[i] = 0.0f;
            g_pt0[i] = 0.0f; g_pt1[i] = 0.0f; g_pt2[i] = 0.0f;
            v1 += W[i] * ss;
            v2 += sl1(a0 * invN, c0 * invN)
                + sl1(a1 * invN, c1 * invN)
                + sl1(a2 * invN, c2 * invN);
        }
        #pragma unroll
        for (int o = 16; o > 0; o >>= 1) {
            v1 += __shfl_down_sync(0xffffffffu, v1, o);
            v2 += __shfl_down_sync(0xffffffffu, v2, o);
        }
        if (tid == 0) {
            out[0] = v1 / (3.0f * (float)N * (float)B);
            out[1] = v2 / ((float)B * 3.0f);
            g_count = 0;
        }
    }
}

extern "C" void kernel_launch(void* const* d_in, const int* in_sizes, int n_in,
                              void* d_out, int out_size)
{
    const float* X = (const float*)d_in[0];   // [B,T,N,3]
    const float* T = (const float*)d_in[1];   // [B,T,N,3]
    const float* W = (const float*)d_in[2];   // [B,T]
    float* out = (float*)d_out;

    const int BT = in_sizes[2];               // 112
    const int N  = in_sizes[0] / (BT * 3);    // 1024
    const int B  = 4;

    const int NSM = 148;
    const int totalUnits = BT * (N / 2);                 // 57344
    const int unitsPerCta = (totalUnits + NSM - 1) / NSM; // 388

    size_t smem = 2 * (size_t)N * sizeof(float4);        // 32 KB (2 banks)
    nn_loss_kernel<<<NSM, 512, smem>>>(X, T, W, out, N, BT, B,
                                       totalUnits, unitsPerCta);
}